// round 11
// baseline (speedup 1.0000x reference)
#include <cuda_runtime.h>
#include <cuda_bf16.h>

// RNN_72541997629806: 5-layer stacked LSTM (H=4), SEQ=610, BATCH=128,
// per-t Linear(4->1) + final FC [5,610] -> out [128,5].
//
// R11: R9's warp-level pipeline (best: 56.5us) re-tiled for SMSP sharing.
//   block = 256 threads = 8 warps -> wid%4 puts TWO warps per SMSP; their
//   independent streams fill each other's stall slots. grid = 16 blocks,
//   8 batch elements per block, one element per warp.
//   Per-warp: lane = stage*4 + j; stages 0-4 LSTM layers, stage 5
//   Linear+FC, lanes 28-31 x-injection; 2 timesteps per shuffle round;
//   packed fma.rn.f32x2 gates; x rows + w_fc in dynamic SMEM (zero-padded).

#define SEQ 610
#define BATCH 128
#define ROUNDS 310           // r = 0..309 ; stage5 t1 = 2*309-10+1 = 609
#define XS_N 624
#define WFC_N 624            // valid data at [10, 620)
#define WARPS_PER_BLOCK 8
#define SMEM_BYTES (WARPS_PER_BLOCK * XS_N * 8 + 5 * WFC_N * 4)

typedef unsigned long long ull;

__device__ __forceinline__ float tanh_fast(float x) {
    float y;
    asm("tanh.approx.f32 %0, %1;" : "=f"(y) : "f"(x));
    return y;
}
__device__ __forceinline__ ull pk2(float lo, float hi) {
    ull r; asm("mov.b64 %0, {%1, %2};" : "=l"(r) : "f"(lo), "f"(hi)); return r;
}
__device__ __forceinline__ ull fma2(ull a, ull b, ull c) {
    ull d; asm("fma.rn.f32x2 %0, %1, %2, %3;" : "=l"(d) : "l"(a), "l"(b), "l"(c)); return d;
}
__device__ __forceinline__ ull mul2(ull a, ull b) {
    ull d; asm("mul.rn.f32x2 %0, %1, %2;" : "=l"(d) : "l"(a), "l"(b)); return d;
}
__device__ __forceinline__ ull add2(ull a, ull b) {
    ull d; asm("add.rn.f32x2 %0, %1, %2;" : "=l"(d) : "l"(a), "l"(b)); return d;
}
__device__ __forceinline__ float hadd2(ull v) {
    float lo, hi; asm("mov.b64 {%0, %1}, %2;" : "=f"(lo), "=f"(hi) : "l"(v)); return lo + hi;
}

__global__ __launch_bounds__(32 * WARPS_PER_BLOCK, 1)
void lstm_warp_kernel(const float* __restrict__ x,      // [128,610,2]
                      const float* __restrict__ w_ih0,  // [16,2]
                      const float* __restrict__ w_ih,   // [4,16,4]
                      const float* __restrict__ w_hh,   // [5,16,4]
                      const float* __restrict__ b_ih,   // [5,16]
                      const float* __restrict__ b_hh,   // [5,16]
                      const float* __restrict__ w_lin,  // [1,4]
                      const float* __restrict__ b_lin,  // [1]
                      const float* __restrict__ w_fc,   // [5,610]
                      const float* __restrict__ b_fc,   // [5]
                      float* __restrict__ out)          // [128,5]
{
    const int tid   = threadIdx.x;
    const int wid   = tid >> 5;              // 0..7
    const int lane  = tid & 31;
    const int stage = lane >> 2;             // 0..7
    const int j     = lane & 3;
    const int b     = blockIdx.x * WARPS_PER_BLOCK + wid;   // batch element
    const int pbase = (lane - 4) & 28;       // base lane of previous stage quad
    const bool isX  = (lane >= 28);

    // ---- dynamic SMEM layout: per-warp x rows, then shared w_fc rows ----
    extern __shared__ __align__(16) char smem[];
    float2* xs_all = reinterpret_cast<float2*>(smem);               // [8][XS_N]
    float*  wfc_s  = reinterpret_cast<float*>(smem + WARPS_PER_BLOCK * XS_N * 8); // [5][WFC_N]
    float2* xs2 = xs_all + wid * XS_N;

    // ---- packed per-lane weights (i/f/o pre-scaled 0.5, sigmoid-via-tanh) ----
    ull wiA0=0,wiA1=0,wiA2=0,wiA3=0, wiB0=0,wiB1=0,wiB2=0,wiB3=0;
    ull whA0=0,whA1=0,whA2=0,whA3=0, whB0=0,whB1=0,whB2=0,whB3=0;
    ull bp0=0, bp1=0, bp2=0, bp3=0;

    if (stage <= 4) {
        #define LQ(q, WIA, WIB, WHA, WHB, BP) do {                                 \
            const int   r  = (q) * 4 + j;                                          \
            const float sc = ((q) == 2) ? 1.0f : 0.5f;                             \
            float w0, w1, w2, w3;                                                  \
            if (stage == 0) {                                                      \
                w0 = sc * w_ih0[r * 2 + 0];  w1 = sc * w_ih0[r * 2 + 1];           \
                w2 = 0.0f;                   w3 = 0.0f;                            \
            } else {                                                               \
                const float* wp = w_ih + (((stage - 1) * 16) + r) * 4;             \
                w0 = sc * wp[0]; w1 = sc * wp[1]; w2 = sc * wp[2]; w3 = sc * wp[3];\
            }                                                                      \
            WIA = pk2(w0, w1);  WIB = pk2(w2, w3);                                 \
            const float* hp = w_hh + ((stage * 16) + r) * 4;                       \
            WHA = pk2(sc * hp[j ^ 0], sc * hp[j ^ 1]);                             \
            WHB = pk2(sc * hp[j ^ 2], sc * hp[j ^ 3]);                             \
            BP  = pk2(sc * (b_ih[stage * 16 + r] + b_hh[stage * 16 + r]), 0.0f);   \
        } while (0)
        LQ(0, wiA0, wiB0, whA0, whB0, bp0);
        LQ(1, wiA1, wiB1, whA1, whB1, bp1);
        LQ(2, wiA2, wiB2, whA2, whB2, bp2);
        LQ(3, wiA3, wiB3, whA3, whB3, bp3);
        #undef LQ
    } else if (stage == 5) {
        wiA0 = pk2(w_lin[0], w_lin[1]);
        wiB0 = pk2(w_lin[2], w_lin[3]);
        bp0  = pk2(b_lin[0], 0.0f);
    }

    // ---- SMEM staging ----
    {
        const float2* xb2 = reinterpret_cast<const float2*>(x + (size_t)b * SEQ * 2);
        for (int i = lane; i < XS_N; i += 32)          // each warp loads its row
            xs2[i] = (i < SEQ) ? xb2[i] : make_float2(0.0f, 0.0f);
        for (int i = tid; i < 5 * WFC_N; i += 32 * WARPS_PER_BLOCK) {  // shared
            const int r = i / WFC_N, c = i - r * WFC_N;
            wfc_s[i] = (c >= 10 && c < SEQ + 10) ? w_fc[r * SEQ + (c - 10)] : 0.0f;
        }
    }
    __syncthreads();

    const float* wA = wfc_s + ((stage == 5) ? j : 0) * WFC_N;
    const float* w4 = wfc_s + 4 * WFC_N;
    float accA = (stage == 5) ? b_fc[j] : 0.0f;
    float accB = (lane == 20) ? b_fc[4] : 0.0f;

    // ---- state: hpubA/hpubB = published h for the round's two timesteps ----
    float hpubA, hpubB, cj = 0.0f;
    {
        const float2 xv0 = xs2[0], xv1 = xs2[1];
        float xcA = (lane & 1) ? xv0.y : xv0.x;  xcA = (lane & 2) ? 0.0f : xcA;
        float xcB = (lane & 1) ? xv1.y : xv1.x;  xcB = (lane & 2) ? 0.0f : xcB;
        hpubA = isX ? xcA : 0.0f;
        hpubB = isX ? xcB : 0.0f;
    }

    // one LSTM cell: packed inputs PA/PB (prev-stage quad), HA/HB (own quad)
    #define CELL(PA, PB, HA, HB, CN, HN, G0OUT) do {                               \
        const float g0 = hadd2(add2(fma2(whA0, HA, fma2(wiA0, PA, bp0)),           \
                                    fma2(whB0, HB, mul2(wiB0, PB))));              \
        const float g1 = hadd2(add2(fma2(whA1, HA, fma2(wiA1, PA, bp1)),           \
                                    fma2(whB1, HB, mul2(wiB1, PB))));              \
        const float g2 = hadd2(add2(fma2(whA2, HA, fma2(wiA2, PA, bp2)),           \
                                    fma2(whB2, HB, mul2(wiB2, PB))));              \
        const float g3 = hadd2(add2(fma2(whA3, HA, fma2(wiA3, PA, bp3)),           \
                                    fma2(whB3, HB, mul2(wiB3, PB))));              \
        const float gt = tanh_fast(g2);                                            \
        const float ig = fmaf(0.5f, tanh_fast(g0), 0.5f);                          \
        const float fg = fmaf(0.5f, tanh_fast(g1), 0.5f);                          \
        const float og = fmaf(0.5f, tanh_fast(g3), 0.5f);                          \
        CN = fmaf(fg, cj, ig * gt);                                                \
        HN = og * tanh_fast(CN);                                                   \
        G0OUT = g0;                                                                \
    } while (0)

    // one round = two timesteps t0 = 2r - 2*stage, t1 = t0+1
    #define ROUND(r, GUARD) do {                                                   \
        const int i0 = 2 * (r);                                                    \
        /* round-start shuffles (all parallel off hpubA/hpubB) */                  \
        const float ob1 = __shfl_xor_sync(0xffffffffu, hpubB, 1);                  \
        const float ob2 = __shfl_xor_sync(0xffffffffu, hpubB, 2);                  \
        const float ob3 = __shfl_xor_sync(0xffffffffu, hpubB, 3);                  \
        const float pA0 = __shfl_sync(0xffffffffu, hpubA, pbase);                  \
        const float pA1 = __shfl_sync(0xffffffffu, hpubA, pbase + 1);              \
        const float pA2 = __shfl_sync(0xffffffffu, hpubA, pbase + 2);              \
        const float pA3 = __shfl_sync(0xffffffffu, hpubA, pbase + 3);              \
        const float pB0 = __shfl_sync(0xffffffffu, hpubB, pbase);                  \
        const float pB1 = __shfl_sync(0xffffffffu, hpubB, pbase + 1);              \
        const float pB2 = __shfl_sync(0xffffffffu, hpubB, pbase + 2);              \
        const float pB3 = __shfl_sync(0xffffffffu, hpubB, pbase + 3);              \
        /* cell t0: own h quad = (hpubB, ob1..3) = h(t0-1) */                      \
        float cn0, hn0, g0c0;                                                      \
        CELL(pk2(pA0, pA1), pk2(pA2, pA3), pk2(hpubB, ob1), pk2(ob2, ob3),         \
             cn0, hn0, g0c0);                                                      \
        float hAn;                                                                 \
        if (GUARD) {                                                               \
            const bool tv = (r) >= stage;                                          \
            cj  = tv ? cn0 : cj;                                                   \
            hAn = tv ? hn0 : 0.0f;                                                 \
        } else { cj = cn0; hAn = hn0; }                                            \
        /* intra-round gather of h(t0) */                                          \
        const float a1 = __shfl_xor_sync(0xffffffffu, hAn, 1);                     \
        const float a2 = __shfl_xor_sync(0xffffffffu, hAn, 2);                     \
        const float a3 = __shfl_xor_sync(0xffffffffu, hAn, 3);                     \
        /* cell t1 */                                                              \
        float cn1, hn1, g0c1;                                                      \
        CELL(pk2(pB0, pB1), pk2(pB2, pB3), pk2(hAn, a1), pk2(a2, a3),              \
             cn1, hn1, g0c1);                                                      \
        float hBn;                                                                 \
        if (GUARD) {                                                               \
            const bool tv = (r) >= stage;                                          \
            cj  = tv ? cn1 : cj;                                                   \
            hBn = tv ? hn1 : 0.0f;                                                 \
        } else { cj = cn1; hBn = hn1; }                                            \
        /* FC accumulate (stage5 g0 = Linear preactivation; zero-headed wfc) */    \
        accA = fmaf(wA[i0],     g0c0, accA);                                       \
        accA = fmaf(wA[i0 + 1], g0c1, accA);                                       \
        accB = fmaf(w4[i0],     g0c0, accB);                                       \
        accB = fmaf(w4[i0 + 1], g0c1, accB);                                       \
        /* injection publish for next round (x(2r+2), x(2r+3)) */                  \
        const float2 xv0 = xs2[i0 + 2], xv1 = xs2[i0 + 3];                         \
        float xcA = (lane & 1) ? xv0.y : xv0.x;  xcA = (lane & 2) ? 0.0f : xcA;    \
        float xcB = (lane & 1) ? xv1.y : xv1.x;  xcB = (lane & 2) ? 0.0f : xcB;    \
        hpubA = isX ? xcA : hAn;                                                   \
        hpubB = isX ? xcB : hBn;                                                   \
    } while (0)

    // prologue: guarded (t0 < 0 for stage > r)
    #pragma unroll 1
    for (int r = 0; r < 5; ++r) ROUND(r, true);
    // steady + tail: select-free (zero-padded x and wfc rows absorb overrun)
    #pragma unroll 2
    for (int r = 5; r < ROUNDS; ++r) ROUND(r, false);

    #undef ROUND
    #undef CELL

    if (stage == 5) out[b * 5 + j] = accA;
    if (lane == 20) out[b * 5 + 4] = accB;
}

extern "C" void kernel_launch(void* const* d_in, const int* in_sizes, int n_in,
                              void* d_out, int out_size) {
    const float* x     = (const float*)d_in[0];
    const float* w_ih0 = (const float*)d_in[1];
    const float* w_ih  = (const float*)d_in[2];
    const float* w_hh  = (const float*)d_in[3];
    const float* b_ih  = (const float*)d_in[4];
    const float* b_hh  = (const float*)d_in[5];
    const float* w_lin = (const float*)d_in[6];
    const float* b_lin = (const float*)d_in[7];
    const float* w_fc  = (const float*)d_in[8];
    const float* b_fc  = (const float*)d_in[9];
    float* out = (float*)d_out;

    cudaFuncSetAttribute(lstm_warp_kernel,
                         cudaFuncAttributeMaxDynamicSharedMemorySize, SMEM_BYTES);

    lstm_warp_kernel<<<BATCH / WARPS_PER_BLOCK, 32 * WARPS_PER_BLOCK, SMEM_BYTES>>>(
        x, w_ih0, w_ih, w_hh, b_ih, b_hh, w_lin, b_lin, w_fc, b_fc, out);
}

// round 12
// speedup vs baseline: 1.2878x; 1.2878x over previous
#include <cuda_runtime.h>
#include <cuda_bf16.h>

// RNN_72541997629806: 5-layer stacked LSTM (H=4), SEQ=610, BATCH=128,
// per-t Linear(4->1) + final FC [5,610] -> out [128,5].
//
// R12: R9's warp pipeline (best: 56.5us), round reordered to hide shuffle
//   latency: shuffles issue first; the previous round's FC accumulation
//   (independent LDS+FFMA) and x publish prep execute in their 26-cyc
//   scoreboard shadow; cells follow. Steady loop unrolled x4 for cross-
//   round scheduling slack. One warp per batch element, 128 x 32.

#define SEQ 610
#define BATCH 128
#define ROUNDS 310           // r = 0..309 ; stage5 t1 = 2*309-10+1 = 609
#define XS_N 624
#define WFC_N 624            // valid data at [10, 620)

typedef unsigned long long ull;

__device__ __forceinline__ float tanh_fast(float x) {
    float y;
    asm("tanh.approx.f32 %0, %1;" : "=f"(y) : "f"(x));
    return y;
}
__device__ __forceinline__ ull pk2(float lo, float hi) {
    ull r; asm("mov.b64 %0, {%1, %2};" : "=l"(r) : "f"(lo), "f"(hi)); return r;
}
__device__ __forceinline__ ull fma2(ull a, ull b, ull c) {
    ull d; asm("fma.rn.f32x2 %0, %1, %2, %3;" : "=l"(d) : "l"(a), "l"(b), "l"(c)); return d;
}
__device__ __forceinline__ ull mul2(ull a, ull b) {
    ull d; asm("mul.rn.f32x2 %0, %1, %2;" : "=l"(d) : "l"(a), "l"(b)); return d;
}
__device__ __forceinline__ ull add2(ull a, ull b) {
    ull d; asm("add.rn.f32x2 %0, %1, %2;" : "=l"(d) : "l"(a), "l"(b)); return d;
}
__device__ __forceinline__ float hadd2(ull v) {
    float lo, hi; asm("mov.b64 {%0, %1}, %2;" : "=f"(lo), "=f"(hi) : "l"(v)); return lo + hi;
}

__global__ __launch_bounds__(32, 1)
void lstm_warp_kernel(const float* __restrict__ x,      // [128,610,2]
                      const float* __restrict__ w_ih0,  // [16,2]
                      const float* __restrict__ w_ih,   // [4,16,4]
                      const float* __restrict__ w_hh,   // [5,16,4]
                      const float* __restrict__ b_ih,   // [5,16]
                      const float* __restrict__ b_hh,   // [5,16]
                      const float* __restrict__ w_lin,  // [1,4]
                      const float* __restrict__ b_lin,  // [1]
                      const float* __restrict__ w_fc,   // [5,610]
                      const float* __restrict__ b_fc,   // [5]
                      float* __restrict__ out)          // [128,5]
{
    const int lane  = threadIdx.x;
    const int stage = lane >> 2;             // 0..7
    const int j     = lane & 3;
    const int b     = blockIdx.x;
    const int pbase = (lane - 4) & 28;       // base lane of previous stage quad
    const bool isX  = (lane >= 28);

    // ---- packed per-lane weights (i/f/o pre-scaled 0.5, sigmoid-via-tanh) ----
    ull wiA0=0,wiA1=0,wiA2=0,wiA3=0, wiB0=0,wiB1=0,wiB2=0,wiB3=0;
    ull whA0=0,whA1=0,whA2=0,whA3=0, whB0=0,whB1=0,whB2=0,whB3=0;
    ull bp0=0, bp1=0, bp2=0, bp3=0;

    if (stage <= 4) {
        #define LQ(q, WIA, WIB, WHA, WHB, BP) do {                                 \
            const int   r  = (q) * 4 + j;                                          \
            const float sc = ((q) == 2) ? 1.0f : 0.5f;                             \
            float w0, w1, w2, w3;                                                  \
            if (stage == 0) {                                                      \
                w0 = sc * w_ih0[r * 2 + 0];  w1 = sc * w_ih0[r * 2 + 1];           \
                w2 = 0.0f;                   w3 = 0.0f;                            \
            } else {                                                               \
                const float* wp = w_ih + (((stage - 1) * 16) + r) * 4;             \
                w0 = sc * wp[0]; w1 = sc * wp[1]; w2 = sc * wp[2]; w3 = sc * wp[3];\
            }                                                                      \
            WIA = pk2(w0, w1);  WIB = pk2(w2, w3);                                 \
            const float* hp = w_hh + ((stage * 16) + r) * 4;                       \
            WHA = pk2(sc * hp[j ^ 0], sc * hp[j ^ 1]);                             \
            WHB = pk2(sc * hp[j ^ 2], sc * hp[j ^ 3]);                             \
            BP  = pk2(sc * (b_ih[stage * 16 + r] + b_hh[stage * 16 + r]), 0.0f);   \
        } while (0)
        LQ(0, wiA0, wiB0, whA0, whB0, bp0);
        LQ(1, wiA1, wiB1, whA1, whB1, bp1);
        LQ(2, wiA2, wiB2, whA2, whB2, bp2);
        LQ(3, wiA3, wiB3, whA3, whB3, bp3);
        #undef LQ
    } else if (stage == 5) {
        wiA0 = pk2(w_lin[0], w_lin[1]);
        wiB0 = pk2(w_lin[2], w_lin[3]);
        bp0  = pk2(b_lin[0], 0.0f);
    }

    // ---- SMEM staging ----
    __shared__ float2 xs2[XS_N];            // [0..609]=x, rest 0
    __shared__ float  wfc_s[5][WFC_N];      // [10..619]=w_fc row, rest 0
    {
        const float2* xb2 = reinterpret_cast<const float2*>(x + (size_t)b * SEQ * 2);
        for (int i = lane; i < XS_N; i += 32)
            xs2[i] = (i < SEQ) ? xb2[i] : make_float2(0.0f, 0.0f);
        #pragma unroll
        for (int r = 0; r < 5; ++r)
            for (int i = lane; i < WFC_N; i += 32)
                wfc_s[r][i] = (i >= 10 && i < SEQ + 10) ? w_fc[r * SEQ + (i - 10)] : 0.0f;
    }
    __syncwarp();

    const float* wA = wfc_s[(stage == 5) ? j : 0];
    const float* w4 = wfc_s[4];
    float accA = (stage == 5) ? b_fc[j] : 0.0f;
    float accB = (lane == 20) ? b_fc[4] : 0.0f;

    // ---- state ----
    float hpubA, hpubB, cj = 0.0f;
    float pg0 = 0.0f, pg1 = 0.0f;           // previous round's g0 values (deferred FC)
    {
        const float2 xv0 = xs2[0], xv1 = xs2[1];
        float xcA = (lane & 1) ? xv0.y : xv0.x;  xcA = (lane & 2) ? 0.0f : xcA;
        float xcB = (lane & 1) ? xv1.y : xv1.x;  xcB = (lane & 2) ? 0.0f : xcB;
        hpubA = isX ? xcA : 0.0f;
        hpubB = isX ? xcB : 0.0f;
    }

    // one LSTM cell: packed inputs PA/PB (prev-stage quad), HA/HB (own quad)
    #define CELL(PA, PB, HA, HB, CN, HN, G0OUT) do {                               \
        const float g0 = hadd2(add2(fma2(whA0, HA, fma2(wiA0, PA, bp0)),           \
                                    fma2(whB0, HB, mul2(wiB0, PB))));              \
        const float g1 = hadd2(add2(fma2(whA1, HA, fma2(wiA1, PA, bp1)),           \
                                    fma2(whB1, HB, mul2(wiB1, PB))));              \
        const float g2 = hadd2(add2(fma2(whA2, HA, fma2(wiA2, PA, bp2)),           \
                                    fma2(whB2, HB, mul2(wiB2, PB))));              \
        const float g3 = hadd2(add2(fma2(whA3, HA, fma2(wiA3, PA, bp3)),           \
                                    fma2(whB3, HB, mul2(wiB3, PB))));              \
        const float gt = tanh_fast(g2);                                            \
        const float ig = fmaf(0.5f, tanh_fast(g0), 0.5f);                          \
        const float fg = fmaf(0.5f, tanh_fast(g1), 0.5f);                          \
        const float og = fmaf(0.5f, tanh_fast(g3), 0.5f);                          \
        CN = fmaf(fg, cj, ig * gt);                                                \
        HN = og * tanh_fast(CN);                                                   \
        G0OUT = g0;                                                                \
    } while (0)

    // one round = two timesteps t0 = 2r - 2*stage, t1 = t0+1.
    // Order: shuffles -> (shadow) deferred FC of prev round + x prep -> cells.
    #define ROUND(r, GUARD) do {                                                   \
        const int i0 = 2 * (r);                                                    \
        /* round-start shuffles (all parallel off hpubA/hpubB) */                  \
        const float ob1 = __shfl_xor_sync(0xffffffffu, hpubB, 1);                  \
        const float ob2 = __shfl_xor_sync(0xffffffffu, hpubB, 2);                  \
        const float ob3 = __shfl_xor_sync(0xffffffffu, hpubB, 3);                  \
        const float pA0 = __shfl_sync(0xffffffffu, hpubA, pbase);                  \
        const float pA1 = __shfl_sync(0xffffffffu, hpubA, pbase + 1);              \
        const float pA2 = __shfl_sync(0xffffffffu, hpubA, pbase + 2);              \
        const float pA3 = __shfl_sync(0xffffffffu, hpubA, pbase + 3);              \
        const float pB0 = __shfl_sync(0xffffffffu, hpubB, pbase);                  \
        const float pB1 = __shfl_sync(0xffffffffu, hpubB, pbase + 1);              \
        const float pB2 = __shfl_sync(0xffffffffu, hpubB, pbase + 2);              \
        const float pB3 = __shfl_sync(0xffffffffu, hpubB, pbase + 3);              \
        /* shuffle shadow: deferred FC acc of PREVIOUS round + x publish prep */   \
        const int ip = GUARD ? ((r) > 0 ? i0 - 2 : 0) : (i0 - 2);                  \
        accA = fmaf(wA[ip],     pg0, accA);                                        \
        accA = fmaf(wA[ip + 1], pg1, accA);                                        \
        accB = fmaf(w4[ip],     pg0, accB);                                        \
        accB = fmaf(w4[ip + 1], pg1, accB);                                        \
        const float2 xv0 = xs2[i0 + 2], xv1 = xs2[i0 + 3];                         \
        float xcA = (lane & 1) ? xv0.y : xv0.x;  xcA = (lane & 2) ? 0.0f : xcA;    \
        float xcB = (lane & 1) ? xv1.y : xv1.x;  xcB = (lane & 2) ? 0.0f : xcB;    \
        /* cell t0: own h quad = (hpubB, ob1..3) = h(t0-1) */                      \
        float cn0, hn0, g0c0;                                                      \
        CELL(pk2(pA0, pA1), pk2(pA2, pA3), pk2(hpubB, ob1), pk2(ob2, ob3),         \
             cn0, hn0, g0c0);                                                      \
        float hAn;                                                                 \
        if (GUARD) {                                                               \
            const bool tv = (r) >= stage;                                          \
            cj  = tv ? cn0 : cj;                                                   \
            hAn = tv ? hn0 : 0.0f;                                                 \
        } else { cj = cn0; hAn = hn0; }                                            \
        /* intra-round gather of h(t0) */                                          \
        const float a1 = __shfl_xor_sync(0xffffffffu, hAn, 1);                     \
        const float a2 = __shfl_xor_sync(0xffffffffu, hAn, 2);                     \
        const float a3 = __shfl_xor_sync(0xffffffffu, hAn, 3);                     \
        /* cell t1 */                                                              \
        float cn1, hn1, g0c1;                                                      \
        CELL(pk2(pB0, pB1), pk2(pB2, pB3), pk2(hAn, a1), pk2(a2, a3),              \
             cn1, hn1, g0c1);                                                      \
        float hBn;                                                                 \
        if (GUARD) {                                                               \
            const bool tv = (r) >= stage;                                          \
            cj  = tv ? cn1 : cj;                                                   \
            hBn = tv ? hn1 : 0.0f;                                                 \
        } else { cj = cn1; hBn = hn1; }                                            \
        /* carry this round's g0s to the next round's shuffle shadow */            \
        pg0 = g0c0;  pg1 = g0c1;                                                   \
        hpubA = isX ? xcA : hAn;                                                   \
        hpubB = isX ? xcB : hBn;                                                   \
    } while (0)

    // prologue: guarded (t0 < 0 for stage > r), fully unrolled (GUARD arms fold)
    #pragma unroll
    for (int r = 0; r < 5; ++r) ROUND(r, true);
    // steady + tail: select-free (zero-padded x and wfc rows absorb overrun)
    #pragma unroll 4
    for (int r = 5; r < ROUNDS; ++r) ROUND(r, false);

    #undef ROUND
    #undef CELL

    // flush last round's deferred FC contribution (indices 618/619, valid)
    accA = fmaf(wA[2 * ROUNDS - 2], pg0, accA);
    accA = fmaf(wA[2 * ROUNDS - 1], pg1, accA);
    accB = fmaf(w4[2 * ROUNDS - 2], pg0, accB);
    accB = fmaf(w4[2 * ROUNDS - 1], pg1, accB);

    if (stage == 5) out[b * 5 + j] = accA;
    if (lane == 20) out[b * 5 + 4] = accB;
}

extern "C" void kernel_launch(void* const* d_in, const int* in_sizes, int n_in,
                              void* d_out, int out_size) {
    const float* x     = (const float*)d_in[0];
    const float* w_ih0 = (const float*)d_in[1];
    const float* w_ih  = (const float*)d_in[2];
    const float* w_hh  = (const float*)d_in[3];
    const float* b_ih  = (const float*)d_in[4];
    const float* b_hh  = (const float*)d_in[5];
    const float* w_lin = (const float*)d_in[6];
    const float* b_lin = (const float*)d_in[7];
    const float* w_fc  = (const float*)d_in[8];
    const float* b_fc  = (const float*)d_in[9];
    float* out = (float*)d_out;

    lstm_warp_kernel<<<BATCH, 32>>>(
        x, w_ih0, w_ih, w_hh, b_ih, b_hh, w_lin, b_lin, w_fc, b_fc, out);
}

// round 13
// speedup vs baseline: 1.2937x; 1.0046x over previous
#include <cuda_runtime.h>
#include <cuda_bf16.h>

// RNN_72541997629806: 5-layer stacked LSTM (H=4), SEQ=610, BATCH=128,
// per-t Linear(4->1) + final FC [5,610] -> out [128,5].
//
// R13: R12 champion (56.0us) with injection machinery shaved:
//   - x staged per-lane: xinj[ss][j] = (j<2 ? x[ss][j] : 0) -> publish is
//     one LDS.32 per timestep, zero ALU selects
//   - gate MUFU order g2,g1,g0,g3 (c-chain consumers first, T3 last)
//   One warp per batch element (128 x 32); 2 timesteps per shuffle round;
//   deferred FC in the shuffle shadow; packed fma.rn.f32x2 gates;
//   zero-padded SMEM, select-free steady loop.

#define SEQ 610
#define BATCH 128
#define ROUNDS 310           // r = 0..309 ; stage5 t1 = 2*309-10+1 = 609
#define XS_N 624
#define WFC_N 624            // valid data at [10, 620)

typedef unsigned long long ull;

__device__ __forceinline__ float tanh_fast(float x) {
    float y;
    asm("tanh.approx.f32 %0, %1;" : "=f"(y) : "f"(x));
    return y;
}
__device__ __forceinline__ ull pk2(float lo, float hi) {
    ull r; asm("mov.b64 %0, {%1, %2};" : "=l"(r) : "f"(lo), "f"(hi)); return r;
}
__device__ __forceinline__ ull fma2(ull a, ull b, ull c) {
    ull d; asm("fma.rn.f32x2 %0, %1, %2, %3;" : "=l"(d) : "l"(a), "l"(b), "l"(c)); return d;
}
__device__ __forceinline__ ull mul2(ull a, ull b) {
    ull d; asm("mul.rn.f32x2 %0, %1, %2;" : "=l"(d) : "l"(a), "l"(b)); return d;
}
__device__ __forceinline__ ull add2(ull a, ull b) {
    ull d; asm("add.rn.f32x2 %0, %1, %2;" : "=l"(d) : "l"(a), "l"(b)); return d;
}
__device__ __forceinline__ float hadd2(ull v) {
    float lo, hi; asm("mov.b64 {%0, %1}, %2;" : "=f"(lo), "=f"(hi) : "l"(v)); return lo + hi;
}

__global__ __launch_bounds__(32, 1)
void lstm_warp_kernel(const float* __restrict__ x,      // [128,610,2]
                      const float* __restrict__ w_ih0,  // [16,2]
                      const float* __restrict__ w_ih,   // [4,16,4]
                      const float* __restrict__ w_hh,   // [5,16,4]
                      const float* __restrict__ b_ih,   // [5,16]
                      const float* __restrict__ b_hh,   // [5,16]
                      const float* __restrict__ w_lin,  // [1,4]
                      const float* __restrict__ b_lin,  // [1]
                      const float* __restrict__ w_fc,   // [5,610]
                      const float* __restrict__ b_fc,   // [5]
                      float* __restrict__ out)          // [128,5]
{
    const int lane  = threadIdx.x;
    const int stage = lane >> 2;             // 0..7
    const int j     = lane & 3;
    const int b     = blockIdx.x;
    const int pbase = (lane - 4) & 28;       // base lane of previous stage quad
    const bool isX  = (lane >= 28);

    // ---- packed per-lane weights (i/f/o pre-scaled 0.5, sigmoid-via-tanh) ----
    ull wiA0=0,wiA1=0,wiA2=0,wiA3=0, wiB0=0,wiB1=0,wiB2=0,wiB3=0;
    ull whA0=0,whA1=0,whA2=0,whA3=0, whB0=0,whB1=0,whB2=0,whB3=0;
    ull bp0=0, bp1=0, bp2=0, bp3=0;

    if (stage <= 4) {
        #define LQ(q, WIA, WIB, WHA, WHB, BP) do {                                 \
            const int   r  = (q) * 4 + j;                                          \
            const float sc = ((q) == 2) ? 1.0f : 0.5f;                             \
            float w0, w1, w2, w3;                                                  \
            if (stage == 0) {                                                      \
                w0 = sc * w_ih0[r * 2 + 0];  w1 = sc * w_ih0[r * 2 + 1];           \
                w2 = 0.0f;                   w3 = 0.0f;                            \
            } else {                                                               \
                const float* wp = w_ih + (((stage - 1) * 16) + r) * 4;             \
                w0 = sc * wp[0]; w1 = sc * wp[1]; w2 = sc * wp[2]; w3 = sc * wp[3];\
            }                                                                      \
            WIA = pk2(w0, w1);  WIB = pk2(w2, w3);                                 \
            const float* hp = w_hh + ((stage * 16) + r) * 4;                       \
            WHA = pk2(sc * hp[j ^ 0], sc * hp[j ^ 1]);                             \
            WHB = pk2(sc * hp[j ^ 2], sc * hp[j ^ 3]);                             \
            BP  = pk2(sc * (b_ih[stage * 16 + r] + b_hh[stage * 16 + r]), 0.0f);   \
        } while (0)
        LQ(0, wiA0, wiB0, whA0, whB0, bp0);
        LQ(1, wiA1, wiB1, whA1, whB1, bp1);
        LQ(2, wiA2, wiB2, whA2, whB2, bp2);
        LQ(3, wiA3, wiB3, whA3, whB3, bp3);
        #undef LQ
    } else if (stage == 5) {
        wiA0 = pk2(w_lin[0], w_lin[1]);
        wiB0 = pk2(w_lin[2], w_lin[3]);
        bp0  = pk2(b_lin[0], 0.0f);
    }

    // ---- SMEM staging ----
    __shared__ float xinj[XS_N][4];         // per-lane injection: [ss][j]
    __shared__ float wfc_s[5][WFC_N];       // [10..619]=w_fc row, rest 0
    {
        const float2* xb2 = reinterpret_cast<const float2*>(x + (size_t)b * SEQ * 2);
        for (int i = lane; i < XS_N; i += 32) {
            const float2 v = (i < SEQ) ? xb2[i] : make_float2(0.0f, 0.0f);
            xinj[i][0] = v.x; xinj[i][1] = v.y;
            xinj[i][2] = 0.0f; xinj[i][3] = 0.0f;
        }
        #pragma unroll
        for (int r = 0; r < 5; ++r)
            for (int i = lane; i < WFC_N; i += 32)
                wfc_s[r][i] = (i >= 10 && i < SEQ + 10) ? w_fc[r * SEQ + (i - 10)] : 0.0f;
    }
    __syncwarp();

    const float* wA = wfc_s[(stage == 5) ? j : 0];
    const float* w4 = wfc_s[4];
    float accA = (stage == 5) ? b_fc[j] : 0.0f;
    float accB = (lane == 20) ? b_fc[4] : 0.0f;

    // ---- state ----
    float hpubA = isX ? xinj[0][j] : 0.0f;
    float hpubB = isX ? xinj[1][j] : 0.0f;
    float cj = 0.0f;
    float pg0 = 0.0f, pg1 = 0.0f;           // previous round's g0 values (deferred FC)

    // one LSTM cell; MUFU order: g2 (gt), g1 (f), g0 (i), g3 (o, last)
    #define CELL(PA, PB, HA, HB, CN, HN, G0OUT) do {                               \
        const float g2 = hadd2(add2(fma2(whA2, HA, fma2(wiA2, PA, bp2)),           \
                                    fma2(whB2, HB, mul2(wiB2, PB))));              \
        const float g1 = hadd2(add2(fma2(whA1, HA, fma2(wiA1, PA, bp1)),           \
                                    fma2(whB1, HB, mul2(wiB1, PB))));              \
        const float g0 = hadd2(add2(fma2(whA0, HA, fma2(wiA0, PA, bp0)),           \
                                    fma2(whB0, HB, mul2(wiB0, PB))));              \
        const float g3 = hadd2(add2(fma2(whA3, HA, fma2(wiA3, PA, bp3)),           \
                                    fma2(whB3, HB, mul2(wiB3, PB))));              \
        const float gt = tanh_fast(g2);                                            \
        const float fg = fmaf(0.5f, tanh_fast(g1), 0.5f);                          \
        const float ig = fmaf(0.5f, tanh_fast(g0), 0.5f);                          \
        const float og = fmaf(0.5f, tanh_fast(g3), 0.5f);                          \
        CN = fmaf(fg, cj, ig * gt);                                                \
        HN = og * tanh_fast(CN);                                                   \
        G0OUT = g0;                                                                \
    } while (0)

    // one round = two timesteps t0 = 2r - 2*stage, t1 = t0+1.
    // Order: shuffles -> (shadow) deferred FC of prev round + x loads -> cells.
    #define ROUND(r, GUARD) do {                                                   \
        const int i0 = 2 * (r);                                                    \
        /* round-start shuffles (all parallel off hpubA/hpubB) */                  \
        const float ob1 = __shfl_xor_sync(0xffffffffu, hpubB, 1);                  \
        const float ob2 = __shfl_xor_sync(0xffffffffu, hpubB, 2);                  \
        const float ob3 = __shfl_xor_sync(0xffffffffu, hpubB, 3);                  \
        const float pA0 = __shfl_sync(0xffffffffu, hpubA, pbase);                  \
        const float pA1 = __shfl_sync(0xffffffffu, hpubA, pbase + 1);              \
        const float pA2 = __shfl_sync(0xffffffffu, hpubA, pbase + 2);              \
        const float pA3 = __shfl_sync(0xffffffffu, hpubA, pbase + 3);              \
        const float pB0 = __shfl_sync(0xffffffffu, hpubB, pbase);                  \
        const float pB1 = __shfl_sync(0xffffffffu, hpubB, pbase + 1);              \
        const float pB2 = __shfl_sync(0xffffffffu, hpubB, pbase + 2);              \
        const float pB3 = __shfl_sync(0xffffffffu, hpubB, pbase + 3);              \
        /* shuffle shadow: deferred FC acc of PREVIOUS round + x loads */          \
        const int ip = GUARD ? ((r) > 0 ? i0 - 2 : 0) : (i0 - 2);                  \
        accA = fmaf(wA[ip],     pg0, accA);                                        \
        accA = fmaf(wA[ip + 1], pg1, accA);                                        \
        accB = fmaf(w4[ip],     pg0, accB);                                        \
        accB = fmaf(w4[ip + 1], pg1, accB);                                        \
        const float xcA = xinj[i0 + 2][j];                                         \
        const float xcB = xinj[i0 + 3][j];                                         \
        /* cell t0: own h quad = (hpubB, ob1..3) = h(t0-1) */                      \
        float cn0, hn0, g0c0;                                                      \
        CELL(pk2(pA0, pA1), pk2(pA2, pA3), pk2(hpubB, ob1), pk2(ob2, ob3),         \
             cn0, hn0, g0c0);                                                      \
        float hAn;                                                                 \
        if (GUARD) {                                                               \
            const bool tv = (r) >= stage;                                          \
            cj  = tv ? cn0 : cj;                                                   \
            hAn = tv ? hn0 : 0.0f;                                                 \
        } else { cj = cn0; hAn = hn0; }                                            \
        /* intra-round gather of h(t0) */                                          \
        const float a1 = __shfl_xor_sync(0xffffffffu, hAn, 1);                     \
        const float a2 = __shfl_xor_sync(0xffffffffu, hAn, 2);                     \
        const float a3 = __shfl_xor_sync(0xffffffffu, hAn, 3);                     \
        /* cell t1 */                                                              \
        float cn1, hn1, g0c1;                                                      \
        CELL(pk2(pB0, pB1), pk2(pB2, pB3), pk2(hAn, a1), pk2(a2, a3),              \
             cn1, hn1, g0c1);                                                      \
        float hBn;                                                                 \
        if (GUARD) {                                                               \
            const bool tv = (r) >= stage;                                          \
            cj  = tv ? cn1 : cj;                                                   \
            hBn = tv ? hn1 : 0.0f;                                                 \
        } else { cj = cn1; hBn = hn1; }                                            \
        /* carry this round's g0s to the next round's shuffle shadow */            \
        pg0 = g0c0;  pg1 = g0c1;                                                   \
        hpubA = isX ? xcA : hAn;                                                   \
        hpubB = isX ? xcB : hBn;                                                   \
    } while (0)

    // prologue: guarded (t0 < 0 for stage > r), fully unrolled (GUARD arms fold)
    #pragma unroll
    for (int r = 0; r < 5; ++r) ROUND(r, true);
    // steady + tail: select-free (zero-padded xinj and wfc rows absorb overrun)
    #pragma unroll 4
    for (int r = 5; r < ROUNDS; ++r) ROUND(r, false);

    #undef ROUND
    #undef CELL

    // flush last round's deferred FC contribution (indices 618/619, valid)
    accA = fmaf(wA[2 * ROUNDS - 2], pg0, accA);
    accA = fmaf(wA[2 * ROUNDS - 1], pg1, accA);
    accB = fmaf(w4[2 * ROUNDS - 2], pg0, accB);
    accB = fmaf(w4[2 * ROUNDS - 1], pg1, accB);

    if (stage == 5) out[b * 5 + j] = accA;
    if (lane == 20) out[b * 5 + 4] = accB;
}

extern "C" void kernel_launch(void* const* d_in, const int* in_sizes, int n_in,
                              void* d_out, int out_size) {
    const float* x     = (const float*)d_in[0];
    const float* w_ih0 = (const float*)d_in[1];
    const float* w_ih  = (const float*)d_in[2];
    const float* w_hh  = (const float*)d_in[3];
    const float* b_ih  = (const float*)d_in[4];
    const float* b_hh  = (const float*)d_in[5];
    const float* w_lin = (const float*)d_in[6];
    const float* b_lin = (const float*)d_in[7];
    const float* w_fc  = (const float*)d_in[8];
    const float* b_fc  = (const float*)d_in[9];
    float* out = (float*)d_out;

    lstm_warp_kernel<<<BATCH, 32>>>(
        x, w_ih0, w_ih, w_hh, b_ih, b_hh, w_lin, b_lin, w_fc, b_fc, out);
}